// round 15
// baseline (speedup 1.0000x reference)
#include <cuda_runtime.h>
#include <cuda_fp16.h>
#include <cstdint>
#include <cstddef>

#define NN 4096
#define FF 128
#define SPLITK 4
#define BK 32
#define KTILES ((NN / SPLITK) / BK)   // 32
#define STAGES 4
#define STAGE_BYTES 16384
#define AF_OFF 0
#define BH_OFF 8192
#define SROWS 8
#define NPAIR (SROWS / 2)

// ---------------- scratch ----------------
__device__ float g_srow[NN];
__device__ float g_scol[NN];
__device__ float2 g_ecs[NN];   // (exp(0.01*scol), exp(scol))
__device__ float g_er1u[NN];
__device__ float g_er2u[NN];
__device__ int   g_irank[NN];
__device__ int   g_mj[NN];
__device__ int4  g_gd[NN];     // sorted-order gather desc {perm, bits(e1), bits(e2), 0}
__device__ float g_part[(size_t)SPLITK * NN * FF];
__device__ __half g_Bh[NN * FF];            // B fp16 [k][n]
__device__ __half g_AttF[(size_t)NN * NN];  // att fp16 (GEMM1 A)
__device__ __half g_AF[(size_t)NN * NN];    // A fp16 (GEMM2 A)

// ---------------- helpers ----------------
__device__ __forceinline__ uint32_t smem_u32(const void* p) {
    uint32_t a;
    asm("{ .reg .u64 t; cvta.to.shared.u64 t, %1; cvt.u32.u64 %0, t; }" : "=r"(a) : "l"(p));
    return a;
}
__device__ __forceinline__ void ldsm4(uint32_t* r, uint32_t a) {
    asm volatile("ldmatrix.sync.aligned.m8n8.x4.shared.b16 {%0,%1,%2,%3}, [%4];"
        : "=r"(r[0]), "=r"(r[1]), "=r"(r[2]), "=r"(r[3]) : "r"(a));
}
__device__ __forceinline__ void ldsm4t(uint32_t* r, uint32_t a) {
    asm volatile("ldmatrix.sync.aligned.m8n8.x4.trans.shared.b16 {%0,%1,%2,%3}, [%4];"
        : "=r"(r[0]), "=r"(r[1]), "=r"(r[2]), "=r"(r[3]) : "r"(a));
}
__device__ __forceinline__ void mma16816(float* d, const uint32_t* a, const uint32_t* b) {
    asm volatile(
        "mma.sync.aligned.m16n8k16.row.col.f32.f16.f16.f32 "
        "{%0,%1,%2,%3}, {%4,%5,%6,%7}, {%8,%9}, {%0,%1,%2,%3};"
        : "+f"(d[0]), "+f"(d[1]), "+f"(d[2]), "+f"(d[3])
        : "r"(a[0]), "r"(a[1]), "r"(a[2]), "r"(a[3]), "r"(b[0]), "r"(b[1]));
}
#define CP16(dst, src) \
    asm volatile("cp.async.cg.shared.global [%0], [%1], 16;" :: "r"(dst), "l"(src))
#define CP_COMMIT() asm volatile("cp.async.commit_group;" ::: "memory")
#define CP_WAIT2() asm volatile("cp.async.wait_group 2;" ::: "memory")
#define CP_WAIT0() asm volatile("cp.async.wait_group 0;" ::: "memory")

// ---------------- K1: XW = X @ W, emit fp16(XW) + sums + exp factors ----------------
__global__ __launch_bounds__(128) void k_xw(const float* __restrict__ X,
                                            const float* __restrict__ W,
                                            const float* __restrict__ av) {
    __shared__ float xr[16][FF];
    int j = threadIdx.x;
    int i0 = blockIdx.x * 16;
#pragma unroll
    for (int r = 0; r < 16; r++) xr[r][j] = X[(size_t)(i0 + r) * FF + j];
    __syncthreads();
    float acc[16];
#pragma unroll
    for (int r = 0; r < 16; r++) acc[r] = 0.f;
    for (int k = 0; k < FF; k++) {
        float w = W[k * FF + j];
#pragma unroll
        for (int r = 0; r < 16; r++) acc[r] += xr[r][k] * w;
    }
#pragma unroll
    for (int r = 0; r < 16; r++)
        g_Bh[(size_t)(i0 + r) * FF + j] = __float2half_rn(acc[r]);

    float ac = av[j], ar = av[FF + j];
    int lane = j & 31, w4 = j >> 5;
    __syncthreads();
#pragma unroll
    for (int r = 0; r < 16; r++) xr[r][j] = acc[r] * ac;
    __syncthreads();
#pragma unroll
    for (int rr = 0; rr < 4; rr++) {
        int r = w4 * 4 + rr;
        float v = xr[r][lane] + xr[r][lane + 32] + xr[r][lane + 64] + xr[r][lane + 96];
#pragma unroll
        for (int off = 16; off; off >>= 1) v += __shfl_down_sync(0xffffffffu, v, off);
        if (lane == 0) {
            g_scol[i0 + r] = v;
            g_ecs[i0 + r] = make_float2(expf(0.01f * v), expf(v));
        }
    }
    __syncthreads();
#pragma unroll
    for (int r = 0; r < 16; r++) xr[r][j] = acc[r] * ar;
    __syncthreads();
#pragma unroll
    for (int rr = 0; rr < 4; rr++) {
        int r = w4 * 4 + rr;
        float v = xr[r][lane] + xr[r][lane + 32] + xr[r][lane + 64] + xr[r][lane + 96];
#pragma unroll
        for (int off = 16; off; off >>= 1) v += __shfl_down_sync(0xffffffffu, v, off);
        if (lane == 0) {
            g_srow[i0 + r] = v;
            g_er1u[i0 + r] = expf(0.01f * v);
            g_er2u[i0 + r] = expf(v);
        }
    }
}

// ---------------- K2: rank-by-count + packed gather descriptors ----------------
__global__ __launch_bounds__(1024) void k_rank() {
    __shared__ float ss[NN];
    int tid = threadIdx.x;
    int lane = tid & 31;
    int wid = tid >> 5;
    int i = blockIdx.x * 32 + wid;
    for (int r = tid; r < NN; r += 1024) ss[r] = g_srow[r];
    __syncthreads();
    float si = ss[i];
    float tj = -g_scol[i];
    int rank = 0, m = 0;
    for (int k = lane; k < NN; k += 32) {
        float sk = ss[k];
        rank += (sk < si) || (sk == si && k < i);
        m += (sk < tj);
    }
#pragma unroll
    for (int off = 16; off; off >>= 1) {
        rank += __shfl_down_sync(0xffffffffu, rank, off);
        m    += __shfl_down_sync(0xffffffffu, m, off);
    }
    if (lane == 0) {
        g_irank[i] = rank;
        g_mj[i] = m;
        int4 d;
        d.x = i;
        d.y = __float_as_int(g_er1u[i]);
        d.z = __float_as_int(g_er2u[i]);
        d.w = 0;
        g_gd[rank] = d;
    }
}

// ---------------- K3: pair-row scan, fused float4 prefix array ----------------
// smem layout (bytes):
//   rowbuf: 2 pair-buffers x 32KB            [0, 65536)
//   sP: float4[NN+1]                         [65536, 131104)
//   wbc: 4 x 32 floats                       [131104, 131616)
#define RB_OFF 0
#define SP_OFF 65536
#define WB_OFF 131104
#define SCAN_SMEM 131616
__global__ __launch_bounds__(1024) void k_scan(const float* __restrict__ A, int row_base) {
    extern __shared__ char smem[];
    float*  rowbuf = (float*)(smem + RB_OFF);
    float4* sP = (float4*)(smem + SP_OFF);   // (Pb0, Pc0, Pb1, Pc1)
    float*  wb0 = (float*)(smem + WB_OFF);
    float*  wc0 = wb0 + 32;
    float*  wb1 = wb0 + 64;
    float*  wc1 = wb0 + 96;

    int tid = threadIdx.x;
    int lane = tid & 31;
    int wid = tid >> 5;
    int base = tid * 4;
    int row0 = row_base + blockIdx.x * SROWS;
    uint32_t rb_base = smem_u32(rowbuf);

    // loop-invariant gather descriptors -> registers
    int   prm[4];
    float ge1[4], ge2[4];
#pragma unroll
    for (int q = 0; q < 4; q++) {
        int4 d = g_gd[base + q];
        prm[q] = d.x;
        ge1[q] = __int_as_float(d.y);
        ge2[q] = __int_as_float(d.z);
    }
    // loop-invariant epilogue constants -> registers
    int   ms[4];
    float2 jc[4];
    {
        int4 mv = *(const int4*)(g_mj + base);
        ms[0] = mv.x; ms[1] = mv.y; ms[2] = mv.z; ms[3] = mv.w;
#pragma unroll
        for (int q = 0; q < 4; q++) jc[q] = g_ecs[base + q];
    }

    // prefetch pair 0 (2 rows = 8192 consecutive floats; 32B/thread)
    {
        const float* src = A + (size_t)row0 * NN + tid * 8;
        CP16(rb_base + tid * 32, src);
        CP16(rb_base + tid * 32 + 16, src + 4);
        CP_COMMIT();
    }

    for (int pr = 0; pr < NPAIR; pr++) {
        int r0 = row0 + 2 * pr;
        size_t orow0 = (size_t)r0 * NN;
        size_t orow1 = orow0 + NN;
        const float* arow0 = rowbuf + (pr & 1) * (2 * NN);
        const float* arow1 = arow0 + NN;

        CP_WAIT0();
        __syncthreads();   // bar A: pair resident

        // prefetch next pair into the other buffer
        if (pr + 1 < NPAIR) {
            const float* src = A + (size_t)(r0 + 2) * NN + tid * 8;
            uint32_t dst = rb_base + ((pr + 1) & 1) * (2 * NN * 4) + tid * 32;
            CP16(dst, src);
            CP16(dst + 16, src + 4);
        }
        CP_COMMIT();

        // emit fp16(A) for both rows
        {
            float4 v0 = *(const float4*)(arow0 + base);
            float4 v1 = *(const float4*)(arow1 + base);
            __half a0 = __float2half_rn(v0.x), a1 = __float2half_rn(v0.y);
            __half a2 = __float2half_rn(v0.z), a3 = __float2half_rn(v0.w);
            __half b0h = __float2half_rn(v1.x), b1h = __float2half_rn(v1.y);
            __half b2h = __float2half_rn(v1.z), b3h = __float2half_rn(v1.w);
            uint2 hv0, hv1;
            hv0.x = (uint32_t)*(uint16_t*)&a0 | ((uint32_t)*(uint16_t*)&a1 << 16);
            hv0.y = (uint32_t)*(uint16_t*)&a2 | ((uint32_t)*(uint16_t*)&a3 << 16);
            hv1.x = (uint32_t)*(uint16_t*)&b0h | ((uint32_t)*(uint16_t*)&b1h << 16);
            hv1.y = (uint32_t)*(uint16_t*)&b2h | ((uint32_t)*(uint16_t*)&b3h << 16);
            *(uint2*)((uint16_t*)g_AF + orow0 + base) = hv0;
            *(uint2*)((uint16_t*)g_AF + orow1 + base) = hv1;
        }

        // gather in sorted order
        float b0[4], c0[4], b1[4], c1[4];
#pragma unroll
        for (int q = 0; q < 4; q++) {
            float a0 = arow0[prm[q]];
            float a1 = arow1[prm[q]];
            b0[q] = a0 * ge1[q]; c0[q] = a0 * ge2[q];
            b1[q] = a1 * ge1[q]; c1[q] = a1 * ge2[q];
        }
        float lb0 = b0[0] + b0[1] + b0[2] + b0[3];
        float lc0 = c0[0] + c0[1] + c0[2] + c0[3];
        float lb1 = b1[0] + b1[1] + b1[2] + b1[3];
        float lc1 = c1[0] + c1[1] + c1[2] + c1[3];

        float sb0 = lb0, sc0 = lc0, sb1 = lb1, sc1 = lc1;
#pragma unroll
        for (int off = 1; off < 32; off <<= 1) {
            float t0 = __shfl_up_sync(0xffffffffu, sb0, off);
            float t1 = __shfl_up_sync(0xffffffffu, sc0, off);
            float t2 = __shfl_up_sync(0xffffffffu, sb1, off);
            float t3 = __shfl_up_sync(0xffffffffu, sc1, off);
            if (lane >= off) { sb0 += t0; sc0 += t1; sb1 += t2; sc1 += t3; }
        }
        if (lane == 31) { wb0[wid] = sb0; wc0[wid] = sc0; wb1[wid] = sb1; wc1[wid] = sc1; }
        __syncthreads();   // bar B: warp sums visible

        // second level: warp 0 -> row0, warp 1 -> row1
        if (wid == 0) {
            float vb = wb0[lane], vc = wc0[lane];
#pragma unroll
            for (int off = 1; off < 32; off <<= 1) {
                float t1 = __shfl_up_sync(0xffffffffu, vb, off);
                float t2 = __shfl_up_sync(0xffffffffu, vc, off);
                if (lane >= off) { vb += t1; vc += t2; }
            }
            wb0[lane] = vb; wc0[lane] = vc;
        } else if (wid == 1) {
            float vb = wb1[lane], vc = wc1[lane];
#pragma unroll
            for (int off = 1; off < 32; off <<= 1) {
                float t1 = __shfl_up_sync(0xffffffffu, vb, off);
                float t2 = __shfl_up_sync(0xffffffffu, vc, off);
                if (lane >= off) { vb += t1; vc += t2; }
            }
            wb1[lane] = vb; wc1[lane] = vc;
        }
        __syncthreads();   // bar B2: second-level prefix ready

        float ob0 = (wid ? wb0[wid - 1] : 0.f) + (sb0 - lb0);
        float oc0 = (wid ? wc0[wid - 1] : 0.f) + (sc0 - lc0);
        float ob1 = (wid ? wb1[wid - 1] : 0.f) + (sb1 - lb1);
        float oc1 = (wid ? wc1[wid - 1] : 0.f) + (sc1 - lc1);
#pragma unroll
        for (int q = 0; q < 4; q++) {
            sP[base + q] = make_float4(ob0, oc0, ob1, oc1);
            ob0 += b0[q]; oc0 += c0[q];
            ob1 += b1[q]; oc1 += c1[q];
        }
        if (tid == 1023) sP[NN] = make_float4(ob0, oc0, ob1, oc1);
        __syncthreads();   // bar C: prefix array ready

        float4 Ct = sP[NN];
        int rank0 = g_irank[r0];
        int rank1 = g_irank[r0 + 1];
        float er10 = g_er1u[r0], er20 = g_er2u[r0];
        float er11 = g_er1u[r0 + 1], er21 = g_er2u[r0 + 1];
        {
            uint16_t h0[4], h1[4];
#pragma unroll
            for (int q = 0; q < 4; q++) {
                int m = ms[q];
                float4 p = sP[m];
                float num0 = jc[q].x * p.x + jc[q].y * (Ct.y - p.y);
                float num1 = jc[q].x * p.z + jc[q].y * (Ct.w - p.w);
                float den0 = (rank0 >= m) ? er20 * jc[q].y : er10 * jc[q].x;
                float den1 = (rank1 >= m) ? er21 * jc[q].y : er11 * jc[q].x;
                float att0 = (num0 != 0.f) ? __fdividef(den0, num0) : 0.f;
                float att1 = (num1 != 0.f) ? __fdividef(den1, num1) : 0.f;
                __half ah0 = __float2half_rn(att0);
                __half ah1 = __float2half_rn(att1);
                h0[q] = *(uint16_t*)&ah0;
                h1[q] = *(uint16_t*)&ah1;
            }
            uint2 hv0, hv1;
            hv0.x = h0[0] | (h0[1] << 16); hv0.y = h0[2] | (h0[3] << 16);
            hv1.x = h1[0] | (h1[1] << 16); hv1.y = h1[2] | (h1[3] << 16);
            *(uint2*)((uint16_t*)g_AttF + orow0 + base) = hv0;
            *(uint2*)((uint16_t*)g_AttF + orow1 + base) = hv1;
        }
        // no end-of-pair barrier: bars A+B of next pair order all reuse
    }
}

// ---------------- K4: HMMA GEMM, single fp16 operands ----------------
__global__ __launch_bounds__(256) void mm_gemm(const __half* __restrict__ Af,
                                               const __half* __restrict__ Bh,
                                               float* __restrict__ Cpart) {
    extern __shared__ char smem[];
    uint32_t sb = smem_u32(smem);
    int tid = threadIdx.x;
    int lane = tid & 31;
    int wid = tid >> 5;
    int wm = wid >> 2;
    int wn = wid & 3;
    int m0 = blockIdx.x * 128;
    int s = blockIdx.y;
    int kbeg = s * (NN / SPLITK);

    auto issue = [&](int t) {
        int kt = kbeg + t * BK;
        uint32_t st = sb + (t & (STAGES - 1)) * STAGE_BYTES;
#pragma unroll
        for (int q = 0; q < 2; q++) {
            int lin = tid + q * 256;
            int rowa = lin >> 2, ca = lin & 3;
            uint32_t dst = st + rowa * 64 + (((ca ^ ((rowa >> 1) & 3))) << 4);
            CP16(dst + AF_OFF, Af + (size_t)(m0 + rowa) * NN + kt + ca * 8);
        }
#pragma unroll
        for (int q = 0; q < 2; q++) {
            int lin = tid + q * 256;
            int kb = lin >> 4, cb = lin & 15;
            uint32_t dst = st + kb * 256 + (((cb ^ (kb & 7))) << 4);
            CP16(dst + BH_OFF, Bh + (size_t)(kt + kb) * FF + cb * 8);
        }
        CP_COMMIT();
    };

    issue(0); issue(1); issue(2);

    float acc[4][4][4];
#pragma unroll
    for (int i = 0; i < 4; i++)
#pragma unroll
        for (int j = 0; j < 4; j++)
#pragma unroll
            for (int r = 0; r < 4; r++) acc[i][j][r] = 0.f;

    for (int t = 0; t < KTILES; t++) {
        CP_WAIT2();
        __syncthreads();
        if (t + 3 < KTILES) issue(t + 3); else CP_COMMIT();

        uint32_t abase = sb + (t & (STAGES - 1)) * STAGE_BYTES;
#pragma unroll
        for (int ks = 0; ks < 2; ks++) {
            uint32_t af[4][4], bhf[2][4];
#pragma unroll
            for (int mt = 0; mt < 4; mt++) {
                int rowa = wm * 64 + mt * 16 + (lane & 7) + ((lane >> 3) & 1) * 8;
                int ca = 2 * ks + (lane >> 4);
                uint32_t addr = abase + rowa * 64 + (((ca ^ ((rowa >> 1) & 3))) << 4);
                ldsm4(af[mt], addr + AF_OFF);
            }
#pragma unroll
            for (int nh = 0; nh < 2; nh++) {
                int kb = ks * 16 + (lane & 7) + ((lane >> 3) & 1) * 8;
                int cb = ((wn * 32 + nh * 16) >> 3) + (lane >> 4);
                uint32_t addr = abase + kb * 256 + (((cb ^ (kb & 7))) << 4);
                ldsm4t(bhf[nh], addr + BH_OFF);
            }
#pragma unroll
            for (int mt = 0; mt < 4; mt++)
#pragma unroll
                for (int nt = 0; nt < 4; nt++)
                    mma16816(acc[mt][nt], af[mt], &bhf[nt >> 1][(nt & 1) * 2]);
        }
    }

    float* C = Cpart + (size_t)s * (NN * FF);
#pragma unroll
    for (int mt = 0; mt < 4; mt++) {
#pragma unroll
        for (int nt = 0; nt < 4; nt++) {
            int rowc = m0 + wm * 64 + mt * 16 + (lane >> 2);
            int colc = wn * 32 + nt * 8 + (lane & 3) * 2;
            *(float2*)(C + (size_t)rowc * FF + colc) =
                make_float2(acc[mt][nt][0], acc[mt][nt][1]);
            *(float2*)(C + (size_t)(rowc + 8) * FF + colc) =
                make_float2(acc[mt][nt][2], acc[mt][nt][3]);
        }
    }
}

// ---------------- K5a: reduce partials -> fp32 out ----------------
__global__ void k_reduce(float* __restrict__ out) {
    int i = blockIdx.x * blockDim.x + threadIdx.x;
    if (i < NN * FF) {
        float s = 0.f;
#pragma unroll
        for (int p = 0; p < SPLITK; p++) s += g_part[(size_t)p * (NN * FF) + i];
        out[i] = s;
    }
}

// ---------------- K5b: reduce partials -> fp16 B operand ----------------
__global__ void k_reduce_conv() {
    int i = blockIdx.x * blockDim.x + threadIdx.x;
    if (i < NN * FF) {
        float s = 0.f;
#pragma unroll
        for (int p = 0; p < SPLITK; p++) s += g_part[(size_t)p * (NN * FF) + i];
        g_Bh[i] = __float2half_rn(s);
    }
}

// ---------------- launcher ----------------
extern "C" void kernel_launch(void* const* d_in, const int* in_sizes, int n_in,
                              void* d_out, int out_size) {
    const float *X = nullptr, *A = nullptr, *W = nullptr, *av = nullptr;
    for (int i = 0; i < n_in; i++) {
        switch (in_sizes[i]) {
            case NN * FF: X = (const float*)d_in[i]; break;
            case NN * NN: A = (const float*)d_in[i]; break;
            case FF * FF: W = (const float*)d_in[i]; break;
            case 2 * FF:  av = (const float*)d_in[i]; break;
            default: break;
        }
    }
    float* H = (float*)d_out;

    __half *dAttF, *dAF, *dBh;
    float* dPart;
    cudaGetSymbolAddress((void**)&dAttF, g_AttF);
    cudaGetSymbolAddress((void**)&dAF, g_AF);
    cudaGetSymbolAddress((void**)&dBh, g_Bh);
    cudaGetSymbolAddress((void**)&dPart, g_part);

    cudaFuncSetAttribute(mm_gemm, cudaFuncAttributeMaxDynamicSharedMemorySize,
                         STAGES * STAGE_BYTES);
    cudaFuncSetAttribute(k_scan, cudaFuncAttributeMaxDynamicSharedMemorySize,
                         SCAN_SMEM);

    k_xw<<<NN / 16, 128>>>(X, W, av);        // launch 1
    k_rank<<<NN / 32, 1024>>>();             // launch 2
    for (int q = 0; q < 4; q++)              // launches 3-6 (#6 = scan, ncu target)
        k_scan<<<128, 1024, SCAN_SMEM>>>(A, q * 1024);

    dim3 grid(NN / 128, SPLITK);
    mm_gemm<<<grid, 256, STAGES * STAGE_BYTES>>>(dAttF, dBh, dPart);  // 7
    k_reduce_conv<<<(NN * FF + 255) / 256, 256>>>();                  // 8
    mm_gemm<<<grid, 256, STAGES * STAGE_BYTES>>>(dAF, dBh, dPart);    // 9
    k_reduce<<<(NN * FF + 255) / 256, 256>>>(H);                      // 10
}

// round 17
// speedup vs baseline: 1.0507x; 1.0507x over previous
#include <cuda_runtime.h>
#include <cuda_fp16.h>
#include <cstdint>
#include <cstddef>

#define NN 4096
#define FF 128
#define SPLITK 4
#define BK 32
#define KTILES ((NN / SPLITK) / BK)   // 32
#define STAGES 4
#define STAGE_BYTES 16384
#define AF_OFF 0
#define BH_OFF 8192
#define SROWS 8
#define NPAIR (SROWS / 2)

// ---------------- scratch ----------------
__device__ float g_srow[NN];
__device__ float g_scol[NN];
__device__ float2 g_ecs[NN];   // (exp(0.01*scol), exp(scol))
__device__ float g_er1u[NN];
__device__ float g_er2u[NN];
__device__ int   g_irank[NN];
__device__ int   g_mj[NN];
__device__ int4  g_gd[NN];     // sorted-order gather desc {perm, bits(e1), bits(e2), 0}
__device__ float g_part[(size_t)SPLITK * NN * FF];
__device__ __half g_Bh[NN * FF];            // B fp16 [k][n]
__device__ __half g_AttF[(size_t)NN * NN];  // att fp16 (GEMM1 A)
__device__ __half g_AF[(size_t)NN * NN];    // A fp16 (GEMM2 A)

// ---------------- helpers ----------------
__device__ __forceinline__ uint32_t smem_u32(const void* p) {
    uint32_t a;
    asm("{ .reg .u64 t; cvta.to.shared.u64 t, %1; cvt.u32.u64 %0, t; }" : "=r"(a) : "l"(p));
    return a;
}
__device__ __forceinline__ void ldsm4(uint32_t* r, uint32_t a) {
    asm volatile("ldmatrix.sync.aligned.m8n8.x4.shared.b16 {%0,%1,%2,%3}, [%4];"
        : "=r"(r[0]), "=r"(r[1]), "=r"(r[2]), "=r"(r[3]) : "r"(a));
}
__device__ __forceinline__ void ldsm4t(uint32_t* r, uint32_t a) {
    asm volatile("ldmatrix.sync.aligned.m8n8.x4.trans.shared.b16 {%0,%1,%2,%3}, [%4];"
        : "=r"(r[0]), "=r"(r[1]), "=r"(r[2]), "=r"(r[3]) : "r"(a));
}
__device__ __forceinline__ void mma16816(float* d, const uint32_t* a, const uint32_t* b) {
    asm volatile(
        "mma.sync.aligned.m16n8k16.row.col.f32.f16.f16.f32 "
        "{%0,%1,%2,%3}, {%4,%5,%6,%7}, {%8,%9}, {%0,%1,%2,%3};"
        : "+f"(d[0]), "+f"(d[1]), "+f"(d[2]), "+f"(d[3])
        : "r"(a[0]), "r"(a[1]), "r"(a[2]), "r"(a[3]), "r"(b[0]), "r"(b[1]));
}
#define CP16(dst, src) \
    asm volatile("cp.async.cg.shared.global [%0], [%1], 16;" :: "r"(dst), "l"(src))
#define CP_COMMIT() asm volatile("cp.async.commit_group;" ::: "memory")
#define CP_WAIT2() asm volatile("cp.async.wait_group 2;" ::: "memory")
#define CP_WAIT1() asm volatile("cp.async.wait_group 1;" ::: "memory")

// ---------------- K1: XW = X @ W, emit fp16(XW) + sums + exp factors ----------------
__global__ __launch_bounds__(128) void k_xw(const float* __restrict__ X,
                                            const float* __restrict__ W,
                                            const float* __restrict__ av) {
    __shared__ float xr[16][FF];
    int j = threadIdx.x;
    int i0 = blockIdx.x * 16;
#pragma unroll
    for (int r = 0; r < 16; r++) xr[r][j] = X[(size_t)(i0 + r) * FF + j];
    __syncthreads();
    float acc[16];
#pragma unroll
    for (int r = 0; r < 16; r++) acc[r] = 0.f;
    for (int k = 0; k < FF; k++) {
        float w = W[k * FF + j];
#pragma unroll
        for (int r = 0; r < 16; r++) acc[r] += xr[r][k] * w;
    }
#pragma unroll
    for (int r = 0; r < 16; r++)
        g_Bh[(size_t)(i0 + r) * FF + j] = __float2half_rn(acc[r]);

    float ac = av[j], ar = av[FF + j];
    int lane = j & 31, w4 = j >> 5;
    __syncthreads();
#pragma unroll
    for (int r = 0; r < 16; r++) xr[r][j] = acc[r] * ac;
    __syncthreads();
#pragma unroll
    for (int rr = 0; rr < 4; rr++) {
        int r = w4 * 4 + rr;
        float v = xr[r][lane] + xr[r][lane + 32] + xr[r][lane + 64] + xr[r][lane + 96];
#pragma unroll
        for (int off = 16; off; off >>= 1) v += __shfl_down_sync(0xffffffffu, v, off);
        if (lane == 0) {
            g_scol[i0 + r] = v;
            g_ecs[i0 + r] = make_float2(expf(0.01f * v), expf(v));
        }
    }
    __syncthreads();
#pragma unroll
    for (int r = 0; r < 16; r++) xr[r][j] = acc[r] * ar;
    __syncthreads();
#pragma unroll
    for (int rr = 0; rr < 4; rr++) {
        int r = w4 * 4 + rr;
        float v = xr[r][lane] + xr[r][lane + 32] + xr[r][lane + 64] + xr[r][lane + 96];
#pragma unroll
        for (int off = 16; off; off >>= 1) v += __shfl_down_sync(0xffffffffu, v, off);
        if (lane == 0) {
            g_srow[i0 + r] = v;
            g_er1u[i0 + r] = expf(0.01f * v);
            g_er2u[i0 + r] = expf(v);
        }
    }
}

// ---------------- K2: rank-by-count + packed gather descriptors ----------------
__global__ __launch_bounds__(1024) void k_rank() {
    __shared__ float ss[NN];
    int tid = threadIdx.x;
    int lane = tid & 31;
    int wid = tid >> 5;
    int i = blockIdx.x * 32 + wid;
    for (int r = tid; r < NN; r += 1024) ss[r] = g_srow[r];
    __syncthreads();
    float si = ss[i];
    float tj = -g_scol[i];
    int rank = 0, m = 0;
    for (int k = lane; k < NN; k += 32) {
        float sk = ss[k];
        rank += (sk < si) || (sk == si && k < i);
        m += (sk < tj);
    }
#pragma unroll
    for (int off = 16; off; off >>= 1) {
        rank += __shfl_down_sync(0xffffffffu, rank, off);
        m    += __shfl_down_sync(0xffffffffu, m, off);
    }
    if (lane == 0) {
        g_irank[i] = rank;
        g_mj[i] = m;
        int4 d;
        d.x = i;
        d.y = __float_as_int(g_er1u[i]);
        d.z = __float_as_int(g_er2u[i]);
        d.w = 0;
        g_gd[rank] = d;
    }
}

// ---------------- K3: pair-row scan with half2-interleaved gather buffer (race-fixed) ----------------
// smem layout (bytes):
//   rowbuf fp32: 2 pair-buffers x 32KB       [0, 65536)
//   hbuf half2: 2 x 16KB                     [65536, 98304)
//   sP: float4[NN+1]                         [98304, 163872)
//   wbc: 4 x 32 floats                       [163872, 164384)
#define RB_OFF 0
#define HB_OFF 65536
#define SP_OFF 98304
#define WB_OFF 163872
#define SCAN_SMEM 164384
__global__ __launch_bounds__(1024) void k_scan(const float* __restrict__ A) {
    extern __shared__ char smem[];
    float*  rowbuf = (float*)(smem + RB_OFF);
    __half2* hbuf  = (__half2*)(smem + HB_OFF);   // [2][NN]
    float4* sP = (float4*)(smem + SP_OFF);        // (Pb0, Pc0, Pb1, Pc1)
    float*  wb0 = (float*)(smem + WB_OFF);
    float*  wc0 = wb0 + 32;
    float*  wb1 = wb0 + 64;
    float*  wc1 = wb0 + 96;

    int tid = threadIdx.x;
    int lane = tid & 31;
    int wid = tid >> 5;
    int base = tid * 4;
    int row0 = blockIdx.x * SROWS;
    uint32_t rb_base = smem_u32(rowbuf);

    // loop-invariant gather descriptors -> registers
    int   prm[4];
    float ge1[4], ge2[4];
#pragma unroll
    for (int q = 0; q < 4; q++) {
        int4 d = g_gd[base + q];
        prm[q] = d.x;
        ge1[q] = __int_as_float(d.y);
        ge2[q] = __int_as_float(d.z);
    }
    // loop-invariant epilogue constants -> registers
    int   ms[4];
    float2 jc[4];
    {
        int4 mv = *(const int4*)(g_mj + base);
        ms[0] = mv.x; ms[1] = mv.y; ms[2] = mv.z; ms[3] = mv.w;
#pragma unroll
        for (int q = 0; q < 4; q++) jc[q] = g_ecs[base + q];
    }

    // convert pair p (resident block-wide in rowbuf[p&1]) -> hbuf[p&1] + emit g_AF
    auto convert_pair = [&](int p) {
        const float* a0r = rowbuf + (p & 1) * (2 * NN);
        const float* a1r = a0r + NN;
        size_t orow0 = (size_t)(row0 + 2 * p) * NN;
        float4 v0 = *(const float4*)(a0r + base);
        float4 v1 = *(const float4*)(a1r + base);
        __half2 h01[4];
        h01[0] = __floats2half2_rn(v0.x, v1.x);
        h01[1] = __floats2half2_rn(v0.y, v1.y);
        h01[2] = __floats2half2_rn(v0.z, v1.z);
        h01[3] = __floats2half2_rn(v0.w, v1.w);
        *(uint4*)(hbuf + (p & 1) * NN + base) = *(uint4*)h01;
        uint32_t u0 = *(uint32_t*)&h01[0], u1 = *(uint32_t*)&h01[1];
        uint32_t u2 = *(uint32_t*)&h01[2], u3 = *(uint32_t*)&h01[3];
        uint2 hv0, hv1;
        hv0.x = (u0 & 0xffffu) | (u1 << 16);
        hv0.y = (u2 & 0xffffu) | (u3 << 16);
        hv1.x = (u0 >> 16) | (u1 & 0xffff0000u);
        hv1.y = (u2 >> 16) | (u3 & 0xffff0000u);
        *(uint2*)((uint16_t*)g_AF + orow0 + base) = hv0;
        *(uint2*)((uint16_t*)g_AF + orow0 + NN + base) = hv1;
    };

    // prologue: prefetch pairs 0 and 1; make pair 0 block-wide visible; convert it
    {
        const float* s0 = A + (size_t)row0 * NN + tid * 8;
        CP16(rb_base + tid * 32, s0);
        CP16(rb_base + tid * 32 + 16, s0 + 4);
        CP_COMMIT();
        const float* s1 = A + (size_t)(row0 + 2) * NN + tid * 8;
        CP16(rb_base + 2 * NN * 4 + tid * 32, s1);
        CP16(rb_base + 2 * NN * 4 + tid * 32 + 16, s1 + 4);
        CP_COMMIT();
        CP_WAIT1();           // pair 0 landed (per-thread)
        __syncthreads();      // pair 0 visible block-wide
        convert_pair(0);
    }

    for (int pr = 0; pr < NPAIR; pr++) {
        int r0 = row0 + 2 * pr;
        size_t orow0 = (size_t)r0 * NN;
        size_t orow1 = orow0 + NN;
        const __half2* hcur = hbuf + (pr & 1) * NN;

        __syncthreads();   // bar A: hbuf[pr] published; rowbuf[pr&1] free

        // prefetch pair pr+2 into the just-freed fp32 buffer
        if (pr + 2 < NPAIR) {
            const float* src = A + (size_t)(r0 + 4) * NN + tid * 8;
            uint32_t dst = rb_base + (pr & 1) * (2 * NN * 4) + tid * 32;
            CP16(dst, src);
            CP16(dst + 16, src + 4);
        }
        CP_COMMIT();

        // gather both rows with ONE random LDS.32 per index
        float b0[4], c0[4], b1[4], c1[4];
#pragma unroll
        for (int q = 0; q < 4; q++) {
            float2 a01 = __half22float2(hcur[prm[q]]);
            b0[q] = a01.x * ge1[q]; c0[q] = a01.x * ge2[q];
            b1[q] = a01.y * ge1[q]; c1[q] = a01.y * ge2[q];
        }
        float lb0 = b0[0] + b0[1] + b0[2] + b0[3];
        float lc0 = c0[0] + c0[1] + c0[2] + c0[3];
        float lb1 = b1[0] + b1[1] + b1[2] + b1[3];
        float lc1 = c1[0] + c1[1] + c1[2] + c1[3];

        float sb0 = lb0, sc0 = lc0, sb1 = lb1, sc1 = lc1;
#pragma unroll
        for (int off = 1; off < 32; off <<= 1) {
            float t0 = __shfl_up_sync(0xffffffffu, sb0, off);
            float t1 = __shfl_up_sync(0xffffffffu, sc0, off);
            float t2 = __shfl_up_sync(0xffffffffu, sb1, off);
            float t3 = __shfl_up_sync(0xffffffffu, sc1, off);
            if (lane >= off) { sb0 += t0; sc0 += t1; sb1 += t2; sc1 += t3; }
        }
        if (lane == 31) { wb0[wid] = sb0; wc0[wid] = sc0; wb1[wid] = sb1; wc1[wid] = sc1; }

        CP_WAIT1();        // pair pr+1 landed (per-thread); bar B below makes it block-wide
        __syncthreads();   // bar B: warp sums visible + pair pr+1 fp32 visible block-wide

        if (wid == 0) {
            float vb = wb0[lane], vc = wc0[lane];
#pragma unroll
            for (int off = 1; off < 32; off <<= 1) {
                float t1 = __shfl_up_sync(0xffffffffu, vb, off);
                float t2 = __shfl_up_sync(0xffffffffu, vc, off);
                if (lane >= off) { vb += t1; vc += t2; }
            }
            wb0[lane] = vb; wc0[lane] = vc;
        } else if (wid == 1) {
            float vb = wb1[lane], vc = wc1[lane];
#pragma unroll
            for (int off = 1; off < 32; off <<= 1) {
                float t1 = __shfl_up_sync(0xffffffffu, vb, off);
                float t2 = __shfl_up_sync(0xffffffffu, vc, off);
                if (lane >= off) { vb += t1; vc += t2; }
            }
            wb1[lane] = vb; wc1[lane] = vc;
        }
        __syncthreads();   // bar B2: second-level prefix ready

        float ob0 = (wid ? wb0[wid - 1] : 0.f) + (sb0 - lb0);
        float oc0 = (wid ? wc0[wid - 1] : 0.f) + (sc0 - lc0);
        float ob1 = (wid ? wb1[wid - 1] : 0.f) + (sb1 - lb1);
        float oc1 = (wid ? wc1[wid - 1] : 0.f) + (sc1 - lc1);
#pragma unroll
        for (int q = 0; q < 4; q++) {
            sP[base + q] = make_float4(ob0, oc0, ob1, oc1);
            ob0 += b0[q]; oc0 += c0[q];
            ob1 += b1[q]; oc1 += c1[q];
        }
        if (tid == 1023) sP[NN] = make_float4(ob0, oc0, ob1, oc1);
        __syncthreads();   // bar C: prefix array ready

        float4 Ct = sP[NN];
        int rank0 = g_irank[r0];
        int rank1 = g_irank[r0 + 1];
        float er10 = g_er1u[r0], er20 = g_er2u[r0];
        float er11 = g_er1u[r0 + 1], er21 = g_er2u[r0 + 1];
        {
            uint16_t h0[4], h1[4];
#pragma unroll
            for (int q = 0; q < 4; q++) {
                int m = ms[q];
                float4 p = sP[m];
                float num0 = jc[q].x * p.x + jc[q].y * (Ct.y - p.y);
                float num1 = jc[q].x * p.z + jc[q].y * (Ct.w - p.w);
                float den0 = (rank0 >= m) ? er20 * jc[q].y : er10 * jc[q].x;
                float den1 = (rank1 >= m) ? er21 * jc[q].y : er11 * jc[q].x;
                float att0 = (num0 != 0.f) ? __fdividef(den0, num0) : 0.f;
                float att1 = (num1 != 0.f) ? __fdividef(den1, num1) : 0.f;
                __half ah0 = __float2half_rn(att0);
                __half ah1 = __float2half_rn(att1);
                h0[q] = *(uint16_t*)&ah0;
                h1[q] = *(uint16_t*)&ah1;
            }
            uint2 hv0, hv1;
            hv0.x = h0[0] | (h0[1] << 16); hv0.y = h0[2] | (h0[3] << 16);
            hv1.x = h1[0] | (h1[1] << 16); hv1.y = h1[2] | (h1[3] << 16);
            *(uint2*)((uint16_t*)g_AttF + orow0 + base) = hv0;
            *(uint2*)((uint16_t*)g_AttF + orow1 + base) = hv1;
        }

        // convert pair pr+1 (block-wide visible since bar B); hbuf[(pr+1)&1] is not read this iter
        if (pr + 1 < NPAIR) convert_pair(pr + 1);
        // next iteration's bar A publishes hbuf[(pr+1)&1] and orders all reuse
    }
}

// ---------------- K4: HMMA GEMM, single fp16 operands ----------------
__global__ __launch_bounds__(256) void mm_gemm(const __half* __restrict__ Af,
                                               const __half* __restrict__ Bh,
                                               float* __restrict__ Cpart) {
    extern __shared__ char smem[];
    uint32_t sb = smem_u32(smem);
    int tid = threadIdx.x;
    int lane = tid & 31;
    int wid = tid >> 5;
    int wm = wid >> 2;
    int wn = wid & 3;
    int m0 = blockIdx.x * 128;
    int s = blockIdx.y;
    int kbeg = s * (NN / SPLITK);

    auto issue = [&](int t) {
        int kt = kbeg + t * BK;
        uint32_t st = sb + (t & (STAGES - 1)) * STAGE_BYTES;
#pragma unroll
        for (int q = 0; q < 2; q++) {
            int lin = tid + q * 256;
            int rowa = lin >> 2, ca = lin & 3;
            uint32_t dst = st + rowa * 64 + (((ca ^ ((rowa >> 1) & 3))) << 4);
            CP16(dst + AF_OFF, Af + (size_t)(m0 + rowa) * NN + kt + ca * 8);
        }
#pragma unroll
        for (int q = 0; q < 2; q++) {
            int lin = tid + q * 256;
            int kb = lin >> 4, cb = lin & 15;
            uint32_t dst = st + kb * 256 + (((cb ^ (kb & 7))) << 4);
            CP16(dst + BH_OFF, Bh + (size_t)(kt + kb) * FF + cb * 8);
        }
        CP_COMMIT();
    };

    issue(0); issue(1); issue(2);

    float acc[4][4][4];
#pragma unroll
    for (int i = 0; i < 4; i++)
#pragma unroll
        for (int j = 0; j < 4; j++)
#pragma unroll
            for (int r = 0; r < 4; r++) acc[i][j][r] = 0.f;

    for (int t = 0; t < KTILES; t++) {
        CP_WAIT2();
        __syncthreads();
        if (t + 3 < KTILES) issue(t + 3); else CP_COMMIT();

        uint32_t abase = sb + (t & (STAGES - 1)) * STAGE_BYTES;
#pragma unroll
        for (int ks = 0; ks < 2; ks++) {
            uint32_t af[4][4], bhf[2][4];
#pragma unroll
            for (int mt = 0; mt < 4; mt++) {
                int rowa = wm * 64 + mt * 16 + (lane & 7) + ((lane >> 3) & 1) * 8;
                int ca = 2 * ks + (lane >> 4);
                uint32_t addr = abase + rowa * 64 + (((ca ^ ((rowa >> 1) & 3))) << 4);
                ldsm4(af[mt], addr + AF_OFF);
            }
#pragma unroll
            for (int nh = 0; nh < 2; nh++) {
                int kb = ks * 16 + (lane & 7) + ((lane >> 3) & 1) * 8;
                int cb = ((wn * 32 + nh * 16) >> 3) + (lane >> 4);
                uint32_t addr = abase + kb * 256 + (((cb ^ (kb & 7))) << 4);
                ldsm4t(bhf[nh], addr + BH_OFF);
            }
#pragma unroll
            for (int mt = 0; mt < 4; mt++)
#pragma unroll
                for (int nt = 0; nt < 4; nt++)
                    mma16816(acc[mt][nt], af[mt], &bhf[nt >> 1][(nt & 1) * 2]);
        }
    }

    float* C = Cpart + (size_t)s * (NN * FF);
#pragma unroll
    for (int mt = 0; mt < 4; mt++) {
#pragma unroll
        for (int nt = 0; nt < 4; nt++) {
            int rowc = m0 + wm * 64 + mt * 16 + (lane >> 2);
            int colc = wn * 32 + nt * 8 + (lane & 3) * 2;
            *(float2*)(C + (size_t)rowc * FF + colc) =
                make_float2(acc[mt][nt][0], acc[mt][nt][1]);
            *(float2*)(C + (size_t)(rowc + 8) * FF + colc) =
                make_float2(acc[mt][nt][2], acc[mt][nt][3]);
        }
    }
}

// ---------------- K5a: reduce partials -> fp32 out ----------------
__global__ void k_reduce(float* __restrict__ out) {
    int i = blockIdx.x * blockDim.x + threadIdx.x;
    if (i < NN * FF) {
        float s = 0.f;
#pragma unroll
        for (int p = 0; p < SPLITK; p++) s += g_part[(size_t)p * (NN * FF) + i];
        out[i] = s;
    }
}

// ---------------- K5b: reduce partials -> fp16 B operand ----------------
__global__ void k_reduce_conv() {
    int i = blockIdx.x * blockDim.x + threadIdx.x;
    if (i < NN * FF) {
        float s = 0.f;
#pragma unroll
        for (int p = 0; p < SPLITK; p++) s += g_part[(size_t)p * (NN * FF) + i];
        g_Bh[i] = __float2half_rn(s);
    }
}

// ---------------- launcher ----------------
extern "C" void kernel_launch(void* const* d_in, const int* in_sizes, int n_in,
                              void* d_out, int out_size) {
    const float *X = nullptr, *A = nullptr, *W = nullptr, *av = nullptr;
    for (int i = 0; i < n_in; i++) {
        switch (in_sizes[i]) {
            case NN * FF: X = (const float*)d_in[i]; break;
            case NN * NN: A = (const float*)d_in[i]; break;
            case FF * FF: W = (const float*)d_in[i]; break;
            case 2 * FF:  av = (const float*)d_in[i]; break;
            default: break;
        }
    }
    float* H = (float*)d_out;

    __half *dAttF, *dAF, *dBh;
    float* dPart;
    cudaGetSymbolAddress((void**)&dAttF, g_AttF);
    cudaGetSymbolAddress((void**)&dAF, g_AF);
    cudaGetSymbolAddress((void**)&dBh, g_Bh);
    cudaGetSymbolAddress((void**)&dPart, g_part);

    cudaFuncSetAttribute(mm_gemm, cudaFuncAttributeMaxDynamicSharedMemorySize,
                         STAGES * STAGE_BYTES);
    cudaFuncSetAttribute(k_scan, cudaFuncAttributeMaxDynamicSharedMemorySize,
                         SCAN_SMEM);

    k_xw<<<NN / 16, 128>>>(X, W, av);
    k_rank<<<NN / 32, 1024>>>();
    k_scan<<<NN / SROWS, 1024, SCAN_SMEM>>>(A);

    dim3 grid(NN / 128, SPLITK);
    mm_gemm<<<grid, 256, STAGES * STAGE_BYTES>>>(dAttF, dBh, dPart);
    k_reduce_conv<<<(NN * FF + 255) / 256, 256>>>();
    mm_gemm<<<grid, 256, STAGES * STAGE_BYTES>>>(dAF, dBh, dPart);
    k_reduce<<<(NN * FF + 255) / 256, 256>>>(H);
}